// round 7
// baseline (speedup 1.0000x reference)
#include <cuda_runtime.h>
#include <cuda_bf16.h>

// ---------------------------------------------------------------------------
// Attention_26379689132660 — fully fused single-kernel version.
//
// Algebraic collapse (R3): everything is affine in the 3-channel inputs z_t,
// so the whole network folds into per-head 3x3 forms:
//   score_h(t) = z7^T M_h z_t + u_h.z_t + r_h.z7 + e_h   (SC*log2e folded in)
//   out        = b_o + sum_h ( G_h zbar_h + g_h ),  zbar_h = softmax-mean z_t
//
// R6 changes:
//  * ONE kernel: each block redundantly computes the 115 derived params
//    (~36 FMA/thread, weights L1-hot) — kills the 4.8us launch/serialize gap.
//  * Pixel loads issued FIRST (6x LDG.128/thread), DRAM latency hidden behind
//    the in-block precompute.
//  * smem transpose: coalesced float4 loads -> conflict-free per-pixel LDS.
//    1 pixel/thread, ~half the regs of R4 -> ~2.3x occupancy.
// ---------------------------------------------------------------------------

struct DerivedParams {
    float M[4][3][3];
    float u[4][3];
    float r[4][3];
    float e[4];
    float G[4][3][3];
    float g[4][3];
    float bo[3];
};

// SC = (1/sqrt(8)) * log2(e), folded into score-domain params.
#define SC_FOLD (0.3535533905932738f * 1.4426950408889634f)

__global__ __launch_bounds__(256) void attn_fused_kernel(
    const float4* __restrict__ Z4,   // (4, 8, 3, 256, 256) as float4
    float* __restrict__ O,           // (4, 3, 256, 256)
    const float* __restrict__ W_in, const float* __restrict__ b_in,
    const float* __restrict__ W_q,  const float* __restrict__ b_q,
    const float* __restrict__ W_k,  const float* __restrict__ b_k,
    const float* __restrict__ W_v,  const float* __restrict__ b_v,
    const float* __restrict__ W_o,  const float* __restrict__ b_o)
{
    __shared__ float zsh[24 * 256];        // [channel][pixel-in-block]
    __shared__ float sA[3][32][3];         // A_q, A_k, A_v
    __shared__ float sCv[3][32];           // c_q, c_k, c_v
    __shared__ DerivedParams sp;

    const int tid    = threadIdx.x;
    const int plane4 = 16384;              // 256*256/4
    const int b      = blockIdx.x >> 8;    // batch (256 blocks per batch)
    const int g4_0   = (blockIdx.x & 255) * 64;   // first float4-group in plane

    // ---- Stage 0: issue this block's pixel loads FIRST (hide DRAM latency
    // behind the precompute below). 1536 float4 per block, 6 per thread,
    // perfectly coalesced.
    const int zbase = b * 24 * plane4 + g4_0;
    float4 v[6];
    #pragma unroll
    for (int k = 0; k < 6; k++) {
        int idx = k * 256 + tid;           // 0..1535
        int ch  = idx >> 6;                // 0..23
        int grp = idx & 63;                // 0..63
        v[k] = __ldg(&Z4[zbase + ch * plane4 + grp]);
    }

    // ---- Stage 1: fold A_X = W_X @ W_in, c_X = W_X b_in + b_X  (per block)
    #pragma unroll
    for (int X = 0; X < 3; X++) {
        const float* W  = (X == 0) ? W_q : (X == 1) ? W_k : W_v;
        const float* bb = (X == 0) ? b_q : (X == 1) ? b_k : b_v;
        if (tid < 96) {                    // A_X[d][c]
            int d = tid / 3, c = tid % 3;
            float s = 0.f;
            #pragma unroll
            for (int i = 0; i < 32; i++) s += W[d * 32 + i] * W_in[i * 3 + c];
            sA[X][d][c] = s;
        } else if (tid < 128) {            // c_X[d]
            int d = tid - 96;
            float s = bb[d];
            #pragma unroll
            for (int i = 0; i < 32; i++) s += W[d * 32 + i] * b_in[i];
            sCv[X][d] = s;
        }
    }
    __syncthreads();

    // ---- Stage 2: per-head 3x3 folds (115 scalars, one thread each)
    if (tid < 36) {                        // M (score-domain: fold SC)
        int h = tid / 9, a = (tid / 3) % 3, bb = tid % 3;
        float s = 0.f;
        #pragma unroll
        for (int j = 0; j < 8; j++) s += sA[0][h * 8 + j][a] * sA[1][h * 8 + j][bb];
        sp.M[h][a][bb] = s * SC_FOLD;
    } else if (tid < 72) {                 // G
        int t2 = tid - 36;
        int h = t2 / 9, o = (t2 / 3) % 3, c = t2 % 3;
        float s = 0.f;
        #pragma unroll
        for (int j = 0; j < 8; j++) s += W_o[o * 32 + h * 8 + j] * sA[2][h * 8 + j][c];
        sp.G[h][o][c] = s;
    } else if (tid < 84) {                 // u
        int t2 = tid - 72;
        int h = t2 / 3, bb = t2 % 3;
        float s = 0.f;
        #pragma unroll
        for (int j = 0; j < 8; j++) s += sCv[0][h * 8 + j] * sA[1][h * 8 + j][bb];
        sp.u[h][bb] = s * SC_FOLD;
    } else if (tid < 96) {                 // r
        int t2 = tid - 84;
        int h = t2 / 3, a = t2 % 3;
        float s = 0.f;
        #pragma unroll
        for (int j = 0; j < 8; j++) s += sA[0][h * 8 + j][a] * sCv[1][h * 8 + j];
        sp.r[h][a] = s * SC_FOLD;
    } else if (tid < 100) {                // e
        int h = tid - 96;
        float s = 0.f;
        #pragma unroll
        for (int j = 0; j < 8; j++) s += sCv[0][h * 8 + j] * sCv[1][h * 8 + j];
        sp.e[h] = s * SC_FOLD;
    } else if (tid < 112) {                // g
        int t2 = tid - 100;
        int h = t2 / 3, o = t2 % 3;
        float s = 0.f;
        #pragma unroll
        for (int j = 0; j < 8; j++) s += W_o[o * 32 + h * 8 + j] * sCv[2][h * 8 + j];
        sp.g[h][o] = s;
    } else if (tid < 115) {                // bo
        sp.bo[tid - 112] = b_o[tid - 112];
    }

    // ---- Stage 3: transpose pixel data through shared.
    // zsh4[ch*64 + grp] == zsh[ch*256 + grp*4 .. +3]
    {
        float4* zsh4 = reinterpret_cast<float4*>(zsh);
        #pragma unroll
        for (int k = 0; k < 6; k++)
            zsh4[k * 256 + tid] = v[k];
    }
    __syncthreads();   // covers both sp and zsh

    // ---- Stage 4: per-pixel attention (1 pixel/thread).
    float z[8][3];
    #pragma unroll
    for (int t = 0; t < 8; t++)
        #pragma unroll
        for (int c = 0; c < 3; c++)
            z[t][c] = zsh[(t * 3 + c) * 256 + tid];  // conflict-free LDS

    float o0 = sp.bo[0], o1 = sp.bo[1], o2 = sp.bo[2];
    const float z70 = z[7][0], z71 = z[7][1], z72 = z[7][2];

    #pragma unroll
    for (int hd = 0; hd < 4; hd++) {
        float vq0 = sp.u[hd][0] + z70*sp.M[hd][0][0] + z71*sp.M[hd][1][0] + z72*sp.M[hd][2][0];
        float vq1 = sp.u[hd][1] + z70*sp.M[hd][0][1] + z71*sp.M[hd][1][1] + z72*sp.M[hd][2][1];
        float vq2 = sp.u[hd][2] + z70*sp.M[hd][0][2] + z71*sp.M[hd][1][2] + z72*sp.M[hd][2][2];
        float rz  = sp.e[hd] + sp.r[hd][0]*z70 + sp.r[hd][1]*z71 + sp.r[hd][2]*z72;

        float sc[8];
        float m = -1e30f;
        #pragma unroll
        for (int t = 0; t < 8; t++) {
            sc[t] = rz + vq0 * z[t][0] + vq1 * z[t][1] + vq2 * z[t][2];
            m = fmaxf(m, sc[t]);
        }
        float esum = 0.f;
        #pragma unroll
        for (int t = 0; t < 8; t++) {
            sc[t] = exp2f(sc[t] - m);      // MUFU.EX2 (log2e pre-folded)
            esum += sc[t];
        }
        const float inv = __fdividef(1.0f, esum);

        float zb0 = 0.f, zb1 = 0.f, zb2 = 0.f;
        #pragma unroll
        for (int t = 0; t < 8; t++) {
            zb0 += sc[t] * z[t][0];
            zb1 += sc[t] * z[t][1];
            zb2 += sc[t] * z[t][2];
        }
        zb0 *= inv; zb1 *= inv; zb2 *= inv;

        o0 += sp.g[hd][0] + sp.G[hd][0][0]*zb0 + sp.G[hd][0][1]*zb1 + sp.G[hd][0][2]*zb2;
        o1 += sp.g[hd][1] + sp.G[hd][1][0]*zb0 + sp.G[hd][1][1]*zb1 + sp.G[hd][1][2]*zb2;
        o2 += sp.g[hd][2] + sp.G[hd][2][0]*zb0 + sp.G[hd][2][1]*zb1 + sp.G[hd][2][2]*zb2;
    }

    // ---- Stage 5: coalesced stores (3 planes).
    const int pix   = ((blockIdx.x & 255) << 8) + tid;   // pixel in plane
    const int obase = b * 3 * 65536 + pix;
    O[obase]          = o0;
    O[obase + 65536]  = o1;
    O[obase + 131072] = o2;
}

extern "C" void kernel_launch(void* const* d_in, const int* in_sizes, int n_in,
                              void* d_out, int out_size)
{
    const float* Z    = (const float*)d_in[0];
    const float* W_in = (const float*)d_in[1];
    const float* b_in = (const float*)d_in[2];
    const float* W_q  = (const float*)d_in[3];
    const float* b_q  = (const float*)d_in[4];
    const float* W_k  = (const float*)d_in[5];
    const float* b_k  = (const float*)d_in[6];
    const float* W_v  = (const float*)d_in[7];
    const float* b_v  = (const float*)d_in[8];
    const float* W_o  = (const float*)d_in[9];
    const float* b_o  = (const float*)d_in[10];

    // 262144 pixels / 256 per block = 1024 blocks, single kernel.
    attn_fused_kernel<<<1024, 256>>>(
        (const float4*)Z, (float*)d_out,
        W_in, b_in, W_q, b_q, W_k, b_k, W_v, b_v, W_o, b_o);
}

// round 10
// speedup vs baseline: 2.3242x; 2.3242x over previous
#include <cuda_runtime.h>
#include <cuda_bf16.h>

// ---------------------------------------------------------------------------
// Attention_26379689132660 — fused single kernel, f32x2 packed math.
//
// Algebraic collapse (R3): everything is affine in the 3-channel z_t, so the
// network folds to per-head 3x3 forms. R7 refinements:
//   score_h(t) = vq_h . z_t,  vq_h = u_h + z7^T M_h      (SC*log2e folded in;
//     the r.z7 + e terms are constant over t -> softmax-invariant -> DROPPED,
//     and scores are then small enough that max-subtraction is unnecessary)
//   out = pC + sum_h G_h zbar_h,  pC = b_o + W_o c_v (head-summed constant)
//
// Implementation:
//  * ONE kernel; each block stages weights to smem COALESCED (fixes R6's
//    L1-bound stride-32 global reads), folds 87 derived scalars, then runs
//    2 pixels/thread with fma.rn.f32x2 (PTX-only FFMA2) — pixel pair lives in
//    the two f32 lanes, loaded directly as LDG.64 float2. Params stored in
//    smem lane-duplicated (u64) so LDS.64 yields ready FFMA2 operands.
//  * z loads issued first; DRAM latency hidden behind the in-block fold.
// ---------------------------------------------------------------------------

typedef unsigned long long u64;

__device__ __forceinline__ u64 pk2(float x, float y) {
    u64 r; asm("mov.b64 %0,{%1,%2};" : "=l"(r) : "f"(x), "f"(y)); return r;
}
__device__ __forceinline__ void up2(u64 v, float& x, float& y) {
    asm("mov.b64 {%0,%1},%2;" : "=f"(x), "=f"(y) : "l"(v));
}
__device__ __forceinline__ u64 f2fma(u64 a, u64 b, u64 c) {
    u64 d; asm("fma.rn.f32x2 %0,%1,%2,%3;" : "=l"(d) : "l"(a), "l"(b), "l"(c)); return d;
}
__device__ __forceinline__ u64 f2mul(u64 a, u64 b) {
    u64 d; asm("mul.rn.f32x2 %0,%1,%2;" : "=l"(d) : "l"(a), "l"(b)); return d;
}
__device__ __forceinline__ u64 f2add(u64 a, u64 b) {
    u64 d; asm("add.rn.f32x2 %0,%1,%2;" : "=l"(d) : "l"(a), "l"(b)); return d;
}
__device__ __forceinline__ float ex2a(float x) {
    float y; asm("ex2.approx.ftz.f32 %0,%1;" : "=f"(y) : "f"(x)); return y;
}
__device__ __forceinline__ float rcpa(float x) {
    float y; asm("rcp.approx.ftz.f32 %0,%1;" : "=f"(y) : "f"(x)); return y;
}

// SC = (1/sqrt(8)) * log2(e), folded into M and u.
#define SC_FOLD (0.3535533905932738f * 1.4426950408889634f)

__global__ __launch_bounds__(256, 2) void attn_fused_kernel(
    const u64* __restrict__ Z2,      // (4,8,3,256,256) viewed as float2/u64
    u64* __restrict__ O2,            // (4,3,256,256)   viewed as float2/u64
    const float* __restrict__ W_in, const float* __restrict__ b_in,
    const float* __restrict__ W_q,  const float* __restrict__ b_q,
    const float* __restrict__ W_k,
    const float* __restrict__ W_v,  const float* __restrict__ b_v,
    const float* __restrict__ W_o,  const float* __restrict__ b_o)
{
    __shared__ float sW[3][1024];          // Wq, Wk, Wv (coalesced-staged)
    __shared__ float sWin[96], sWo[96];
    __shared__ float sbq[32], sbv[32], sbin[32];
    __shared__ float sA[3][96];            // A_X[d*3+c] = (W_X @ W_in)
    __shared__ float sCq[32], sCv[32];     // c_q, c_v  (c_k unused)
    __shared__ u64 pM[4][9], pU[4][3], pG[4][9], pC[3];  // lane-duplicated

    const int tid    = threadIdx.x;
    const int plane2 = 32768;              // float2 per 256x256 plane
    const int b      = blockIdx.x >> 7;    // 128 blocks per batch
    const int g0     = (blockIdx.x & 127) * 256;

    // ---- Stage 0: issue this thread's 24 pixel-pair loads FIRST.
    // LDG.64, perfectly coalesced; latency hidden behind the fold below.
    u64 z2[8][3];
    {
        const u64* p = Z2 + (size_t)b * 24 * plane2 + g0 + tid;
        #pragma unroll
        for (int t = 0; t < 8; t++)
            #pragma unroll
            for (int c = 0; c < 3; c++)
                z2[t][c] = __ldg(p + (t * 3 + c) * plane2);
    }

    // ---- Stage 0b: stage weights into smem, COALESCED.
    #pragma unroll
    for (int i = tid; i < 1024; i += 256) {
        sW[0][i] = W_q[i]; sW[1][i] = W_k[i]; sW[2][i] = W_v[i];
    }
    if (tid < 96)       { sWin[tid] = W_in[tid]; sWo[tid] = W_o[tid]; }
    else if (tid < 128) sbq[tid - 96]   = b_q[tid - 96];
    else if (tid < 160) sbv[tid - 128]  = b_v[tid - 128];
    else if (tid < 192) sbin[tid - 160] = b_in[tid - 160];
    __syncthreads();

    // ---- Stage 1: A_X = W_X @ W_in (288 vals), c_q / c_v (64 vals).
    for (int idx = tid; idx < 288; idx += 256) {
        int X = idx / 96, r = idx % 96, d = r / 3, c = r % 3;
        float s = 0.f;
        #pragma unroll
        for (int i = 0; i < 32; i++) s += sW[X][d * 32 + i] * sWin[i * 3 + c];
        sA[X][r] = s;
    }
    if (tid < 64) {
        int X = (tid < 32) ? 0 : 2;        // q or v
        int d = tid & 31;
        float s = (tid < 32) ? sbq[d] : sbv[d];
        #pragma unroll
        for (int i = 0; i < 32; i++) s += sW[X][d * 32 + i] * sbin[i];
        if (tid < 32) sCq[d] = s; else sCv[d] = s;
    }
    __syncthreads();

    // ---- Stage 2: 87 derived scalars, stored lane-duplicated (u64).
    if (tid < 36) {                        // M[h][a][c] (fold SC)
        int h = tid / 9, a = (tid / 3) % 3, c = tid % 3;
        float s = 0.f;
        #pragma unroll
        for (int j = 0; j < 8; j++)
            s += sA[0][(h * 8 + j) * 3 + a] * sA[1][(h * 8 + j) * 3 + c];
        s *= SC_FOLD;
        pM[h][a * 3 + c] = pk2(s, s);
    } else if (tid < 48) {                 // u[h][c] (fold SC)
        int t2 = tid - 36, h = t2 / 3, c = t2 % 3;
        float s = 0.f;
        #pragma unroll
        for (int j = 0; j < 8; j++) s += sCq[h * 8 + j] * sA[1][(h * 8 + j) * 3 + c];
        s *= SC_FOLD;
        pU[h][c] = pk2(s, s);
    } else if (tid < 84) {                 // G[h][o][c]
        int t2 = tid - 48, h = t2 / 9, o = (t2 / 3) % 3, c = t2 % 3;
        float s = 0.f;
        #pragma unroll
        for (int j = 0; j < 8; j++) s += sWo[o * 32 + h * 8 + j] * sA[2][(h * 8 + j) * 3 + c];
        pG[h][o * 3 + c] = pk2(s, s);
    } else if (tid < 87) {                 // pC[o] = b_o + W_o . c_v (all heads)
        int o = tid - 84;
        float s = b_o[o];
        #pragma unroll
        for (int d = 0; d < 32; d++) s += sWo[o * 32 + d] * sCv[d];
        pC[o] = pk2(s, s);
    }
    __syncthreads();

    // ---- Stage 3: attention math, 2 pixels per thread in f32x2 lanes.
    u64 o0 = pC[0], o1 = pC[1], o2 = pC[2];

    #pragma unroll
    for (int hd = 0; hd < 4; hd++) {
        // vq_c = u_c + sum_a z7_a * M[a][c]   (score-domain, SC folded)
        u64 vq0 = f2fma(z2[7][0], pM[hd][0], pU[hd][0]);
        vq0     = f2fma(z2[7][1], pM[hd][3], vq0);
        vq0     = f2fma(z2[7][2], pM[hd][6], vq0);
        u64 vq1 = f2fma(z2[7][0], pM[hd][1], pU[hd][1]);
        vq1     = f2fma(z2[7][1], pM[hd][4], vq1);
        vq1     = f2fma(z2[7][2], pM[hd][7], vq1);
        u64 vq2 = f2fma(z2[7][0], pM[hd][2], pU[hd][2]);
        vq2     = f2fma(z2[7][1], pM[hd][5], vq2);
        vq2     = f2fma(z2[7][2], pM[hd][8], vq2);

        // scores -> exp2 (no max-subtraction: t-constant terms dropped, so
        // scores are small; ratio is mathematically unchanged)
        u64 sc[8];
        #pragma unroll
        for (int t = 0; t < 8; t++) {
            u64 s = f2mul(vq0, z2[t][0]);
            s = f2fma(vq1, z2[t][1], s);
            s = f2fma(vq2, z2[t][2], s);
            float a, c; up2(s, a, c);
            sc[t] = pk2(ex2a(a), ex2a(c));
        }
        u64 esA = f2add(f2add(sc[0], sc[1]), f2add(sc[2], sc[3]));
        u64 esB = f2add(f2add(sc[4], sc[5]), f2add(sc[6], sc[7]));
        u64 es  = f2add(esA, esB);
        float e0, e1; up2(es, e0, e1);
        u64 pinv = pk2(rcpa(e0), rcpa(e1));

        u64 zb0 = f2mul(sc[0], z2[0][0]);
        u64 zb1 = f2mul(sc[0], z2[0][1]);
        u64 zb2 = f2mul(sc[0], z2[0][2]);
        #pragma unroll
        for (int t = 1; t < 8; t++) {
            zb0 = f2fma(sc[t], z2[t][0], zb0);
            zb1 = f2fma(sc[t], z2[t][1], zb1);
            zb2 = f2fma(sc[t], z2[t][2], zb2);
        }
        zb0 = f2mul(zb0, pinv); zb1 = f2mul(zb1, pinv); zb2 = f2mul(zb2, pinv);

        o0 = f2fma(pG[hd][0], zb0, o0);
        o0 = f2fma(pG[hd][1], zb1, o0);
        o0 = f2fma(pG[hd][2], zb2, o0);
        o1 = f2fma(pG[hd][3], zb0, o1);
        o1 = f2fma(pG[hd][4], zb1, o1);
        o1 = f2fma(pG[hd][5], zb2, o1);
        o2 = f2fma(pG[hd][6], zb0, o2);
        o2 = f2fma(pG[hd][7], zb1, o2);
        o2 = f2fma(pG[hd][8], zb2, o2);
    }

    // ---- Stage 4: coalesced STG.64 (pixel pair per store), 3 planes.
    u64* op = O2 + (size_t)b * 3 * plane2 + g0 + tid;
    op[0]          = o0;
    op[plane2]     = o1;
    op[2 * plane2] = o2;
}

extern "C" void kernel_launch(void* const* d_in, const int* in_sizes, int n_in,
                              void* d_out, int out_size)
{
    const float* Z    = (const float*)d_in[0];
    const float* W_in = (const float*)d_in[1];
    const float* b_in = (const float*)d_in[2];
    const float* W_q  = (const float*)d_in[3];
    const float* b_q  = (const float*)d_in[4];
    const float* W_k  = (const float*)d_in[5];
    // b_k (d_in[6]) provably unused: its contribution is constant over t
    const float* W_v  = (const float*)d_in[7];
    const float* b_v  = (const float*)d_in[8];
    const float* W_o  = (const float*)d_in[9];
    const float* b_o  = (const float*)d_in[10];

    // 262144 pixels / 2 per thread / 256 threads = 512 blocks, one kernel.
    attn_fused_kernel<<<512, 256>>>(
        (const u64*)Z, (u64*)d_out,
        W_in, b_in, W_q, b_q, W_k, W_v, b_v, W_o, b_o);
}